// round 1
// baseline (speedup 1.0000x reference)
#include <cuda_runtime.h>
#include <math.h>

// Problem constants
#define BB 4
#define LL 2048
#define MM 8192           // B*L tokens
#define EE 1024
#define VV 64
#define NT 2016
#define LN_EPS 1e-5f

// Scratch (device globals; no dynamic allocation allowed)
__device__ float g_h[(size_t)MM * EE];        // 32 MB post-LN hidden
__device__ float g_theta[(size_t)MM * NT];    // 66 MB softplus(Theta) rows

// ---------------------------------------------------------------------------
// Generic tiled SGEMM:  C[M,N] = epi(A[M,K] @ B[N,K]^T + bias[N])
// BLK_M=128, BLK_N=128, BLK_K=16, 256 threads, 8x8 per thread.
// M must be a multiple of 128 (true here: 8192). N may be ragged (2016, 64).
// EPI: 0 = none, 1 = exact gelu, 2 = softplus
// ---------------------------------------------------------------------------
#define BLM 128
#define BLN 128
#define BLK 16

template<int EPI>
__global__ __launch_bounds__(256)
void sgemm_bt(const float* __restrict__ A, const float* __restrict__ B,
              const float* __restrict__ bias, float* __restrict__ C,
              int M, int N, int K)
{
    __shared__ float As[BLK][BLM];
    __shared__ float Bs[BLK][BLN];

    const int tid = threadIdx.x;
    const int tx = tid & 15;          // 0..15 -> N micro
    const int ty = tid >> 4;          // 0..15 -> M micro
    const int bm = blockIdx.x * BLM;
    const int bn = blockIdx.y * BLN;

    const int lr = tid >> 2;          // 0..63  loader row
    const int lc = (tid & 3) * 4;     // 0,4,8,12 loader col (float4)

    float acc[8][8];
#pragma unroll
    for (int i = 0; i < 8; ++i)
#pragma unroll
        for (int j = 0; j < 8; ++j) acc[i][j] = 0.0f;

    for (int k0 = 0; k0 < K; k0 += BLK) {
        // A tile (no row guard: M % 128 == 0)
#pragma unroll
        for (int it = 0; it < 2; ++it) {
            int r = lr + it * 64;
            float4 v = *(const float4*)&A[(size_t)(bm + r) * K + k0 + lc];
            As[lc + 0][r] = v.x; As[lc + 1][r] = v.y;
            As[lc + 2][r] = v.z; As[lc + 3][r] = v.w;
        }
        // B tile (row guard for ragged N)
#pragma unroll
        for (int it = 0; it < 2; ++it) {
            int r = lr + it * 64;
            int gn = bn + r;
            float4 v = make_float4(0.f, 0.f, 0.f, 0.f);
            if (gn < N) v = *(const float4*)&B[(size_t)gn * K + k0 + lc];
            Bs[lc + 0][r] = v.x; Bs[lc + 1][r] = v.y;
            Bs[lc + 2][r] = v.z; Bs[lc + 3][r] = v.w;
        }
        __syncthreads();

#pragma unroll
        for (int k = 0; k < BLK; ++k) {
            float a[8], b[8];
            *(float4*)&a[0] = *(const float4*)&As[k][ty * 8];
            *(float4*)&a[4] = *(const float4*)&As[k][ty * 8 + 4];
            *(float4*)&b[0] = *(const float4*)&Bs[k][tx * 8];
            *(float4*)&b[4] = *(const float4*)&Bs[k][tx * 8 + 4];
#pragma unroll
            for (int i = 0; i < 8; ++i)
#pragma unroll
                for (int j = 0; j < 8; ++j)
                    acc[i][j] = fmaf(a[i], b[j], acc[i][j]);
        }
        __syncthreads();
    }

    // epilogue
#pragma unroll
    for (int i = 0; i < 8; ++i) {
        int row = bm + ty * 8 + i;
#pragma unroll
        for (int j = 0; j < 8; ++j) {
            int col = bn + tx * 8 + j;
            if (col < N) {
                float x = acc[i][j] + bias[col];
                if (EPI == 1) {
                    // exact gelu: 0.5*x*(1+erf(x/sqrt(2)))
                    x = 0.5f * x * (1.0f + erff(x * 0.70710678118654752440f));
                } else if (EPI == 2) {
                    // softplus = max(x,0) + log1p(exp(-|x|))
                    x = fmaxf(x, 0.0f) + log1pf(expf(-fabsf(x)));
                }
                C[(size_t)row * N + col] = x;
            }
        }
    }
}

// ---------------------------------------------------------------------------
// LayerNorm (in-place) over rows of E=1024.  256 threads, 1 float4 per thread.
// ---------------------------------------------------------------------------
__global__ __launch_bounds__(256)
void ln_kernel(float* __restrict__ h, const float* __restrict__ g,
               const float* __restrict__ b)
{
    const int row = blockIdx.x;
    const int tid = threadIdx.x;
    float* p = h + (size_t)row * EE;

    float4 v = *(const float4*)&p[tid * 4];

    __shared__ float red[8];
    __shared__ float mu_s, rstd_s;

    // mean
    float s = v.x + v.y + v.z + v.w;
#pragma unroll
    for (int o = 16; o; o >>= 1) s += __shfl_xor_sync(0xffffffffu, s, o);
    if ((tid & 31) == 0) red[tid >> 5] = s;
    __syncthreads();
    if (tid < 32) {
        float t = (tid < 8) ? red[tid] : 0.0f;
#pragma unroll
        for (int o = 4; o; o >>= 1) t += __shfl_xor_sync(0xffffffffu, t, o);
        if (tid == 0) mu_s = t * (1.0f / EE);
    }
    __syncthreads();
    const float mu = mu_s;

    // variance
    float dx = v.x - mu, dy = v.y - mu, dz = v.z - mu, dw = v.w - mu;
    float s2 = dx * dx + dy * dy + dz * dz + dw * dw;
#pragma unroll
    for (int o = 16; o; o >>= 1) s2 += __shfl_xor_sync(0xffffffffu, s2, o);
    __syncthreads();   // protect red[] reuse
    if ((tid & 31) == 0) red[tid >> 5] = s2;
    __syncthreads();
    if (tid < 32) {
        float t = (tid < 8) ? red[tid] : 0.0f;
#pragma unroll
        for (int o = 4; o; o >>= 1) t += __shfl_xor_sync(0xffffffffu, t, o);
        if (tid == 0) rstd_s = rsqrtf(t * (1.0f / EE) + LN_EPS);
    }
    __syncthreads();
    const float rstd = rstd_s;

    const int c = tid * 4;
    float4 gg = *(const float4*)&g[c];
    float4 bb = *(const float4*)&b[c];
    float4 o;
    o.x = dx * rstd * gg.x + bb.x;
    o.y = dy * rstd * gg.y + bb.y;
    o.z = dz * rstd * gg.z + bb.z;
    o.w = dw * rstd * gg.w + bb.w;
    *(float4*)&p[c] = o;
}

// ---------------------------------------------------------------------------
// Softmax (in-place) over rows of V=64. One warp per row, 8 rows per block.
// ---------------------------------------------------------------------------
__global__ __launch_bounds__(256)
void softmax_kernel(float* __restrict__ logits)
{
    const int row = blockIdx.x * 8 + (threadIdx.x >> 5);
    const int lane = threadIdx.x & 31;
    float* p = logits + (size_t)row * VV;

    float2 v = *(const float2*)&p[lane * 2];
    float m = fmaxf(v.x, v.y);
#pragma unroll
    for (int o = 16; o; o >>= 1) m = fmaxf(m, __shfl_xor_sync(0xffffffffu, m, o));
    float e0 = expf(v.x - m), e1 = expf(v.y - m);
    float s = e0 + e1;
#pragma unroll
    for (int o = 16; o; o >>= 1) s += __shfl_xor_sync(0xffffffffu, s, o);
    float inv = 1.0f / s;
    float2 o2; o2.x = e0 * inv; o2.y = e1 * inv;
    *(float2*)&p[lane * 2] = o2;
}

// ---------------------------------------------------------------------------
// Q assembly: per token, build 64x64 Q from Theta row (upper-tri packed) and pi.
// Q[i][j] = S[i][j]*sqrt(pi_j)/sqrt(pi_i) (i != j), Q[i][i] = -rowsum.
// 256 threads/block: thread t handles row i=t/4, 16 cols starting at (t%4)*16.
// ---------------------------------------------------------------------------
__global__ __launch_bounds__(256)
void qasm_kernel(const float* __restrict__ theta, const float* __restrict__ pi,
                 float* __restrict__ Q)
{
    const int tok = blockIdx.x;
    __shared__ float th[NT];
    __shared__ float spi[VV];
    __shared__ float rspi[VV];

    const int tid = threadIdx.x;
    const float* tp = theta + (size_t)tok * NT;
    for (int i = tid; i < NT / 4; i += 256)
        ((float4*)th)[i] = ((const float4*)tp)[i];
    if (tid < VV) {
        float p = pi[(size_t)tok * VV + tid];
        float sp = sqrtf(p);
        spi[tid] = sp;
        rspi[tid] = 1.0f / sp;
    }
    __syncthreads();

    const int i = tid >> 2;
    const int jb = (tid & 3) * 16;
    const float ri = rspi[i];
    const int offi = i * (127 - i) / 2;   // packed upper-tri row offset (k=1)

    float vals[16];
    float s = 0.0f;
#pragma unroll
    for (int jj = 0; jj < 16; ++jj) {
        int j = jb + jj;
        float sv;
        if (j == i)      sv = 0.0f;
        else if (i < j)  sv = th[offi + j - i - 1];
        else             sv = th[j * (127 - j) / 2 + i - j - 1];
        float qv = sv * spi[j] * ri;
        vals[jj] = qv;
        s += qv;
    }
    // sum across the 4 threads covering row i (contiguous lanes, tid%4 aligned)
    s += __shfl_xor_sync(0xffffffffu, s, 1);
    s += __shfl_xor_sync(0xffffffffu, s, 2);

    float* out = Q + (size_t)tok * (VV * VV) + i * VV + jb;
#pragma unroll
    for (int jj = 0; jj < 16; ++jj)
        out[jj] = (jb + jj == i) ? -s : vals[jj];
}

// ---------------------------------------------------------------------------
// Launch
// ---------------------------------------------------------------------------
extern "C" void kernel_launch(void* const* d_in, const int* in_sizes, int n_in,
                              void* d_out, int out_size)
{
    const float* hx = (const float*)d_in[0];   // (B,L,E)
    const float* Wd = (const float*)d_in[1];   // (E,E)
    const float* bd = (const float*)d_in[2];   // (E,)
    const float* lg = (const float*)d_in[3];   // (E,)
    const float* lb = (const float*)d_in[4];   // (E,)
    const float* Wt = (const float*)d_in[5];   // (V,E)
    const float* bt = (const float*)d_in[6];   // (V,)
    const float* WT = (const float*)d_in[7];   // (NT,E)
    const float* bT = (const float*)d_in[8];   // (NT,)

    float* out = (float*)d_out;
    float* Q  = out;                                // (B,L,V,V)
    float* pi = out + (size_t)MM * VV * VV;         // (B,L,V)

    float* hbuf = nullptr;
    float* thbuf = nullptr;
    cudaGetSymbolAddress((void**)&hbuf, g_h);
    cudaGetSymbolAddress((void**)&thbuf, g_theta);

    // 1) h = gelu(hx @ Wd^T + bd)
    sgemm_bt<1><<<dim3(MM / BLM, EE / BLN), 256>>>(hx, Wd, bd, hbuf, MM, EE, EE);
    // 2) LayerNorm in-place
    ln_kernel<<<MM, 256>>>(hbuf, lg, lb);
    // 3) logits = h @ Wt^T + bt  (written into pi region, softmaxed in-place)
    sgemm_bt<0><<<dim3(MM / BLM, 1), 256>>>(hbuf, Wt, bt, pi, MM, VV, EE);
    softmax_kernel<<<MM / 8, 256>>>(pi);
    // 4) Theta = softplus(h @ WT^T + bT)
    sgemm_bt<2><<<dim3(MM / BLM, (NT + BLN - 1) / BLN), 256>>>(hbuf, WT, bT, thbuf, MM, NT, EE);
    // 5) Assemble Q
    qasm_kernel<<<MM, 256>>>(thbuf, pi, Q);
}

// round 2
// speedup vs baseline: 2.1093x; 2.1093x over previous
#include <cuda_runtime.h>
#include <cuda_bf16.h>
#include <math.h>
#include <stdint.h>

// Problem constants
#define MM 8192           // B*L tokens
#define EE 1024
#define VV 64
#define NTT 2016
#define LN_EPS 1e-5f

// ---------------------------------------------------------------------------
// Scratch (device globals; no dynamic allocation allowed)
// ---------------------------------------------------------------------------
__device__ float g_h[(size_t)MM * EE];          // 32 MB gelu output (pre-LN)
__device__ float g_theta[(size_t)MM * NTT];     // 66 MB softplus(Theta)
__device__ __nv_bfloat16 g_hx_hi[(size_t)MM * EE], g_hx_lo[(size_t)MM * EE];
__device__ __nv_bfloat16 g_h_hi [(size_t)MM * EE], g_h_lo [(size_t)MM * EE];
__device__ __nv_bfloat16 g_Wd_hi[EE * EE],  g_Wd_lo[EE * EE];
__device__ __nv_bfloat16 g_Wt_hi[VV * EE],  g_Wt_lo[VV * EE];
__device__ __nv_bfloat16 g_WT_hi[NTT * EE], g_WT_lo[NTT * EE];

// ---------------------------------------------------------------------------
// fp32 -> (bf16 hi, bf16 lo) split, vectorized float4
// ---------------------------------------------------------------------------
__global__ __launch_bounds__(256)
void split_kernel(const float* __restrict__ x, __nv_bfloat16* __restrict__ hi,
                  __nv_bfloat16* __restrict__ lo, int n4)
{
    int i = blockIdx.x * 256 + threadIdx.x;
    if (i >= n4) return;
    float4 v = ((const float4*)x)[i];
    __nv_bfloat16 h[4], l[4];
    float vv[4] = {v.x, v.y, v.z, v.w};
#pragma unroll
    for (int k = 0; k < 4; ++k) {
        h[k] = __float2bfloat16(vv[k]);
        l[k] = __float2bfloat16(vv[k] - __bfloat162float(h[k]));
    }
    ((uint2*)hi)[i] = *(uint2*)h;
    ((uint2*)lo)[i] = *(uint2*)l;
}

// ---------------------------------------------------------------------------
// Tensor-core GEMM:  C[M,N] = epi(A[M,K] @ B[N,K]^T + bias[N])
// A,B given as bf16 hi/lo splits; fp32 accum; 3-term product.
// BM=128, BN=128, BK=32, 256 thr (8 warps, 4x2), warp tile 32x64.
// EPI: 0 none, 1 exact gelu, 2 softplus
// ---------------------------------------------------------------------------
#define GBM 128
#define GBN 128
#define GBK 32
#define ASTR 40          // smem row stride in bf16 elems (32 + 8 pad)

__device__ __forceinline__ uint32_t sptr(const void* p) {
    return (uint32_t)__cvta_generic_to_shared(p);
}
__device__ __forceinline__ void ldsm4(uint32_t* r, uint32_t a) {
    asm volatile("ldmatrix.sync.aligned.m8n8.x4.shared.b16 {%0,%1,%2,%3}, [%4];"
        : "=r"(r[0]), "=r"(r[1]), "=r"(r[2]), "=r"(r[3]) : "r"(a));
}
__device__ __forceinline__ void mma16816(float* c, const uint32_t* a,
                                         uint32_t b0, uint32_t b1) {
    asm volatile(
        "mma.sync.aligned.m16n8k16.row.col.f32.bf16.bf16.f32 "
        "{%0,%1,%2,%3}, {%4,%5,%6,%7}, {%8,%9}, {%0,%1,%2,%3};"
        : "+f"(c[0]), "+f"(c[1]), "+f"(c[2]), "+f"(c[3])
        : "r"(a[0]), "r"(a[1]), "r"(a[2]), "r"(a[3]), "r"(b0), "r"(b1));
}

template<int EPI>
__global__ __launch_bounds__(256)
void gemm_bf16x3(const __nv_bfloat16* __restrict__ Ah, const __nv_bfloat16* __restrict__ Al,
                 const __nv_bfloat16* __restrict__ Bh, const __nv_bfloat16* __restrict__ Bl,
                 const float* __restrict__ bias, float* __restrict__ C,
                 int M, int N, int K)
{
    __shared__ __nv_bfloat16 sAh[GBM * ASTR];
    __shared__ __nv_bfloat16 sAl[GBM * ASTR];
    __shared__ __nv_bfloat16 sBh[GBN * ASTR];
    __shared__ __nv_bfloat16 sBl[GBN * ASTR];

    const int tid  = threadIdx.x;
    const int warp = tid >> 5;
    const int lane = tid & 31;
    const int wm   = warp >> 1;     // 0..3 -> m offset wm*32
    const int wn   = warp & 1;      // 0..1 -> n offset wn*64
    const int bm   = blockIdx.x * GBM;
    const int bn   = blockIdx.y * GBN;

    // loader coords: each thread loads 8 contiguous bf16 (16B), 64 rows/pass
    const int lr = tid >> 2;
    const int lc = (tid & 3) * 8;

    const size_t aOff0 = (size_t)(bm + lr) * K + lc;
    const size_t aOff1 = aOff0 + (size_t)64 * K;
    const int gn0 = bn + lr, gn1 = bn + lr + 64;
    const size_t bOff0 = (size_t)gn0 * K + lc;
    const size_t bOff1 = (size_t)gn1 * K + lc;
    const bool bok0 = gn0 < N, bok1 = gn1 < N;

    float acc[2][8][4];
#pragma unroll
    for (int i = 0; i < 2; ++i)
#pragma unroll
        for (int j = 0; j < 8; ++j)
#pragma unroll
            for (int k = 0; k < 4; ++k) acc[i][j][k] = 0.0f;

    const uint4 z4 = make_uint4(0u, 0u, 0u, 0u);
    uint4 rAh0, rAh1, rAl0, rAl1, rBh0, rBh1, rBl0, rBl1;

    // prologue: load kt=0
    {
        rAh0 = *(const uint4*)(Ah + aOff0);
        rAh1 = *(const uint4*)(Ah + aOff1);
        rAl0 = *(const uint4*)(Al + aOff0);
        rAl1 = *(const uint4*)(Al + aOff1);
        rBh0 = bok0 ? *(const uint4*)(Bh + bOff0) : z4;
        rBh1 = bok1 ? *(const uint4*)(Bh + bOff1) : z4;
        rBl0 = bok0 ? *(const uint4*)(Bl + bOff0) : z4;
        rBl1 = bok1 ? *(const uint4*)(Bl + bOff1) : z4;
    }
    *(uint4*)(sAh + lr * ASTR + lc)        = rAh0;
    *(uint4*)(sAh + (lr + 64) * ASTR + lc) = rAh1;
    *(uint4*)(sAl + lr * ASTR + lc)        = rAl0;
    *(uint4*)(sAl + (lr + 64) * ASTR + lc) = rAl1;
    *(uint4*)(sBh + lr * ASTR + lc)        = rBh0;
    *(uint4*)(sBh + (lr + 64) * ASTR + lc) = rBh1;
    *(uint4*)(sBl + lr * ASTR + lc)        = rBl0;
    *(uint4*)(sBl + (lr + 64) * ASTR + lc) = rBl1;
    __syncthreads();

    const int nk = K / GBK;
    for (int kt = 0; kt < nk; ++kt) {
        // prefetch next tile into regs while computing current
        if (kt + 1 < nk) {
            const int ko = (kt + 1) * GBK;
            rAh0 = *(const uint4*)(Ah + aOff0 + ko);
            rAh1 = *(const uint4*)(Ah + aOff1 + ko);
            rAl0 = *(const uint4*)(Al + aOff0 + ko);
            rAl1 = *(const uint4*)(Al + aOff1 + ko);
            rBh0 = bok0 ? *(const uint4*)(Bh + bOff0 + ko) : z4;
            rBh1 = bok1 ? *(const uint4*)(Bh + bOff1 + ko) : z4;
            rBl0 = bok0 ? *(const uint4*)(Bl + bOff0 + ko) : z4;
            rBl1 = bok1 ? *(const uint4*)(Bl + bOff1 + ko) : z4;
        }

#pragma unroll
        for (int ks = 0; ks < 2; ++ks) {
            uint32_t aH[2][4], aL[2][4];
#pragma unroll
            for (int mt = 0; mt < 2; ++mt) {
                const int row  = wm * 32 + mt * 16 + (lane & 15);
                const int eoff = ks * 16 + (lane >> 4) * 8;
                ldsm4(aH[mt], sptr(sAh + row * ASTR + eoff));
                ldsm4(aL[mt], sptr(sAl + row * ASTR + eoff));
            }
#pragma unroll
            for (int jj = 0; jj < 4; ++jj) {
                const int brow  = wn * 64 + jj * 16 + ((lane >> 4) ? 8 : 0) + (lane & 7);
                const int beoff = ks * 16 + (((lane >> 3) & 1) ? 8 : 0);
                uint32_t bH[4], bL[4];
                ldsm4(bH, sptr(sBh + brow * ASTR + beoff));
                ldsm4(bL, sptr(sBl + brow * ASTR + beoff));
#pragma unroll
                for (int mt = 0; mt < 2; ++mt) {
#pragma unroll
                    for (int sub = 0; sub < 2; ++sub) {
                        float* c = acc[mt][jj * 2 + sub];
                        mma16816(c, aH[mt], bH[sub * 2], bH[sub * 2 + 1]);
                        mma16816(c, aH[mt], bL[sub * 2], bL[sub * 2 + 1]);
                        mma16816(c, aL[mt], bH[sub * 2], bH[sub * 2 + 1]);
                    }
                }
            }
        }

        if (kt + 1 < nk) {
            __syncthreads();
            *(uint4*)(sAh + lr * ASTR + lc)        = rAh0;
            *(uint4*)(sAh + (lr + 64) * ASTR + lc) = rAh1;
            *(uint4*)(sAl + lr * ASTR + lc)        = rAl0;
            *(uint4*)(sAl + (lr + 64) * ASTR + lc) = rAl1;
            *(uint4*)(sBh + lr * ASTR + lc)        = rBh0;
            *(uint4*)(sBh + (lr + 64) * ASTR + lc) = rBh1;
            *(uint4*)(sBl + lr * ASTR + lc)        = rBl0;
            *(uint4*)(sBl + (lr + 64) * ASTR + lc) = rBl1;
            __syncthreads();
        }
    }

    // epilogue
#pragma unroll
    for (int mt = 0; mt < 2; ++mt) {
#pragma unroll
        for (int nt = 0; nt < 8; ++nt) {
            const int row = bm + wm * 32 + mt * 16 + (lane >> 2);
            const int col = bn + wn * 64 + nt * 8 + (lane & 3) * 2;
            if (col < N) {
                const float b0 = bias[col], b1 = bias[col + 1];
#pragma unroll
                for (int half = 0; half < 2; ++half) {  // rows row, row+8
                    float x0 = acc[mt][nt][half * 2 + 0] + b0;
                    float x1 = acc[mt][nt][half * 2 + 1] + b1;
                    if (EPI == 1) {
                        x0 = 0.5f * x0 * (1.0f + erff(x0 * 0.70710678118654752440f));
                        x1 = 0.5f * x1 * (1.0f + erff(x1 * 0.70710678118654752440f));
                    } else if (EPI == 2) {
                        x0 = fmaxf(x0, 0.0f) + log1pf(expf(-fabsf(x0)));
                        x1 = fmaxf(x1, 0.0f) + log1pf(expf(-fabsf(x1)));
                    }
                    float2 o2; o2.x = x0; o2.y = x1;
                    *(float2*)&C[(size_t)(row + half * 8) * N + col] = o2;
                }
            }
        }
    }
}

// ---------------------------------------------------------------------------
// LayerNorm over rows of E=1024, fused with bf16 hi/lo split of the output.
// ---------------------------------------------------------------------------
__global__ __launch_bounds__(256)
void ln_split_kernel(const float* __restrict__ h, const float* __restrict__ g,
                     const float* __restrict__ b,
                     __nv_bfloat16* __restrict__ hi, __nv_bfloat16* __restrict__ lo)
{
    const int row = blockIdx.x;
    const int tid = threadIdx.x;
    const float* p = h + (size_t)row * EE;

    float4 v = ((const float4*)p)[tid];

    __shared__ float red[8];
    __shared__ float mu_s, rstd_s;

    float s = v.x + v.y + v.z + v.w;
#pragma unroll
    for (int o = 16; o; o >>= 1) s += __shfl_xor_sync(0xffffffffu, s, o);
    if ((tid & 31) == 0) red[tid >> 5] = s;
    __syncthreads();
    if (tid < 32) {
        float t = (tid < 8) ? red[tid] : 0.0f;
#pragma unroll
        for (int o = 4; o; o >>= 1) t += __shfl_xor_sync(0xffffffffu, t, o);
        if (tid == 0) mu_s = t * (1.0f / EE);
    }
    __syncthreads();
    const float mu = mu_s;

    float dx = v.x - mu, dy = v.y - mu, dz = v.z - mu, dw = v.w - mu;
    float s2 = dx * dx + dy * dy + dz * dz + dw * dw;
#pragma unroll
    for (int o = 16; o; o >>= 1) s2 += __shfl_xor_sync(0xffffffffu, s2, o);
    __syncthreads();
    if ((tid & 31) == 0) red[tid >> 5] = s2;
    __syncthreads();
    if (tid < 32) {
        float t = (tid < 8) ? red[tid] : 0.0f;
#pragma unroll
        for (int o = 4; o; o >>= 1) t += __shfl_xor_sync(0xffffffffu, t, o);
        if (tid == 0) rstd_s = rsqrtf(t * (1.0f / EE) + LN_EPS);
    }
    __syncthreads();
    const float rstd = rstd_s;

    const int c = tid * 4;
    float4 gg = *(const float4*)&g[c];
    float4 bb = *(const float4*)&b[c];
    float o[4];
    o[0] = dx * rstd * gg.x + bb.x;
    o[1] = dy * rstd * gg.y + bb.y;
    o[2] = dz * rstd * gg.z + bb.z;
    o[3] = dw * rstd * gg.w + bb.w;

    __nv_bfloat16 hb[4], lb4[4];
#pragma unroll
    for (int k = 0; k < 4; ++k) {
        hb[k]  = __float2bfloat16(o[k]);
        lb4[k] = __float2bfloat16(o[k] - __bfloat162float(hb[k]));
    }
    ((uint2*)(hi + (size_t)row * EE))[tid] = *(uint2*)hb;
    ((uint2*)(lo + (size_t)row * EE))[tid] = *(uint2*)lb4;
}

// ---------------------------------------------------------------------------
// Softmax (in-place) over rows of V=64. One warp per row, 8 rows per block.
// ---------------------------------------------------------------------------
__global__ __launch_bounds__(256)
void softmax_kernel(float* __restrict__ logits)
{
    const int row = blockIdx.x * 8 + (threadIdx.x >> 5);
    const int lane = threadIdx.x & 31;
    float* p = logits + (size_t)row * VV;

    float2 v = *(const float2*)&p[lane * 2];
    float m = fmaxf(v.x, v.y);
#pragma unroll
    for (int o = 16; o; o >>= 1) m = fmaxf(m, __shfl_xor_sync(0xffffffffu, m, o));
    float e0 = expf(v.x - m), e1 = expf(v.y - m);
    float s = e0 + e1;
#pragma unroll
    for (int o = 16; o; o >>= 1) s += __shfl_xor_sync(0xffffffffu, s, o);
    float inv = 1.0f / s;
    float2 o2; o2.x = e0 * inv; o2.y = e1 * inv;
    *(float2*)&p[lane * 2] = o2;
}

// ---------------------------------------------------------------------------
// Q assembly (unchanged from R1, verified correct)
// ---------------------------------------------------------------------------
__global__ __launch_bounds__(256)
void qasm_kernel(const float* __restrict__ theta, const float* __restrict__ pi,
                 float* __restrict__ Q)
{
    const int tok = blockIdx.x;
    __shared__ float th[NTT];
    __shared__ float spi[VV];
    __shared__ float rspi[VV];

    const int tid = threadIdx.x;
    const float* tp = theta + (size_t)tok * NTT;
    for (int i = tid; i < NTT / 4; i += 256)
        ((float4*)th)[i] = ((const float4*)tp)[i];
    if (tid < VV) {
        float p = pi[(size_t)tok * VV + tid];
        float sp = sqrtf(p);
        spi[tid] = sp;
        rspi[tid] = 1.0f / sp;
    }
    __syncthreads();

    const int i = tid >> 2;
    const int jb = (tid & 3) * 16;
    const float ri = rspi[i];
    const int offi = i * (127 - i) / 2;

    float vals[16];
    float s = 0.0f;
#pragma unroll
    for (int jj = 0; jj < 16; ++jj) {
        int j = jb + jj;
        float sv;
        if (j == i)      sv = 0.0f;
        else if (i < j)  sv = th[offi + j - i - 1];
        else             sv = th[j * (127 - j) / 2 + i - j - 1];
        float qv = sv * spi[j] * ri;
        vals[jj] = qv;
        s += qv;
    }
    s += __shfl_xor_sync(0xffffffffu, s, 1);
    s += __shfl_xor_sync(0xffffffffu, s, 2);

    float* out = Q + (size_t)tok * (VV * VV) + i * VV + jb;
#pragma unroll
    for (int jj = 0; jj < 16; ++jj)
        out[jj] = (jb + jj == i) ? -s : vals[jj];
}

// ---------------------------------------------------------------------------
// Launch
// ---------------------------------------------------------------------------
extern "C" void kernel_launch(void* const* d_in, const int* in_sizes, int n_in,
                              void* d_out, int out_size)
{
    const float* hx = (const float*)d_in[0];   // (B,L,E)
    const float* Wd = (const float*)d_in[1];   // (E,E)
    const float* bd = (const float*)d_in[2];
    const float* lg = (const float*)d_in[3];
    const float* lb = (const float*)d_in[4];
    const float* Wt = (const float*)d_in[5];   // (V,E)
    const float* bt = (const float*)d_in[6];
    const float* WT = (const float*)d_in[7];   // (NT,E)
    const float* bT = (const float*)d_in[8];

    float* out = (float*)d_out;
    float* Q  = out;
    float* pi = out + (size_t)MM * VV * VV;

    float *hbuf, *thbuf;
    __nv_bfloat16 *hx_hi, *hx_lo, *h_hi, *h_lo, *Wd_hi, *Wd_lo, *Wt_hi, *Wt_lo, *WT_hi, *WT_lo;
    cudaGetSymbolAddress((void**)&hbuf,  g_h);
    cudaGetSymbolAddress((void**)&thbuf, g_theta);
    cudaGetSymbolAddress((void**)&hx_hi, g_hx_hi);
    cudaGetSymbolAddress((void**)&hx_lo, g_hx_lo);
    cudaGetSymbolAddress((void**)&h_hi,  g_h_hi);
    cudaGetSymbolAddress((void**)&h_lo,  g_h_lo);
    cudaGetSymbolAddress((void**)&Wd_hi, g_Wd_hi);
    cudaGetSymbolAddress((void**)&Wd_lo, g_Wd_lo);
    cudaGetSymbolAddress((void**)&Wt_hi, g_Wt_hi);
    cudaGetSymbolAddress((void**)&Wt_lo, g_Wt_lo);
    cudaGetSymbolAddress((void**)&WT_hi, g_WT_hi);
    cudaGetSymbolAddress((void**)&WT_lo, g_WT_lo);

    // 0) split inputs to bf16 hi/lo
    split_kernel<<<(MM * EE / 4 + 255) / 256, 256>>>(hx, hx_hi, hx_lo, MM * EE / 4);
    split_kernel<<<(EE * EE / 4 + 255) / 256, 256>>>(Wd, Wd_hi, Wd_lo, EE * EE / 4);
    split_kernel<<<(VV * EE / 4 + 255) / 256, 256>>>(Wt, Wt_hi, Wt_lo, VV * EE / 4);
    split_kernel<<<(NTT * EE / 4 + 255) / 256, 256>>>(WT, WT_hi, WT_lo, NTT * EE / 4);

    // 1) h = gelu(hx @ Wd^T + bd)   (fp32 out)
    gemm_bf16x3<1><<<dim3(MM / GBM, EE / GBN), 256>>>(
        hx_hi, hx_lo, Wd_hi, Wd_lo, bd, hbuf, MM, EE, EE);

    // 2) LayerNorm + split h to bf16 hi/lo
    ln_split_kernel<<<MM, 256>>>(hbuf, lg, lb, h_hi, h_lo);

    // 3) logits = h @ Wt^T + bt -> softmax (in pi region)
    gemm_bf16x3<0><<<dim3(MM / GBM, 1), 256>>>(
        h_hi, h_lo, Wt_hi, Wt_lo, bt, pi, MM, VV, EE);
    softmax_kernel<<<MM / 8, 256>>>(pi);

    // 4) Theta = softplus(h @ WT^T + bT)
    gemm_bf16x3<2><<<dim3(MM / GBM, (NTT + GBN - 1) / GBN), 256>>>(
        h_hi, h_lo, WT_hi, WT_lo, bT, thbuf, MM, NTT, EE);

    // 5) Assemble Q
    qasm_kernel<<<MM, 256>>>(thbuf, pi, Q);
}